// round 5
// baseline (speedup 1.0000x reference)
#include <cuda_runtime.h>
#include <math.h>

#define N_ROWS 8192
#define DIM    128

#define NT 128           // rows per block
#define OT 64            // cols per block
#define KC 32            // i-chunk staged in smem
#define NCH (DIM / KC)   // 4 chunks
#define THREADS 512
#define NR 4             // rows per thread
#define OR 4             // cols per thread (2 packed pairs)
#define NTP 129          // padded float2 row stride

// ---- packed weights (prep kernel output), separate planes so o-adjacent
//      values pack directly into f32x2 operands ----
// gGa: g (clipped) ; gWy: ln2*Wr ; gWz: ln2*Wi ; gP: -pi*g*Wi ; gQ: pi*g*Wr
__device__ float gGa[DIM * DIM];
__device__ float gWy[DIM * DIM];
__device__ float gWz[DIM * DIM];
__device__ float gP [DIM * DIM];
__device__ float gQ [DIM * DIM];

__global__ void NPU_prep_kernel(const float* __restrict__ Wr,
                                const float* __restrict__ Wi,
                                const float* __restrict__ G) {
    int idx = blockIdx.x * blockDim.x + threadIdx.x;
    if (idx >= DIM * DIM) return;
    float g = fminf(fmaxf(G[idx], 0.0f), 1.0f);
    float wr = Wr[idx];
    float wi = Wi[idx];
    const float LN2 = 0.69314718055994530942f;
    const float PI  = 3.14159265358979323846f;
    gGa[idx] = g;
    gWy[idx] = LN2 * wr;
    gWz[idx] = LN2 * wi;
    gP [idx] = -PI * g * wi;
    gQ [idx] = PI * g * wr;
}

// ---- smem layout: 5 weight planes [KC][OT] + duplicated row planes ----
#define SM_PLANE     (KC * OT * 4)          // 8192 B each
#define SM_G_OFF     0
#define SM_WY_OFF    (1 * SM_PLANE)
#define SM_WZ_OFF    (2 * SM_PLANE)
#define SM_P_OFF     (3 * SM_PLANE)
#define SM_Q_OFF     (4 * SM_PLANE)
#define SM_ROWS_OFF  (5 * SM_PLANE)
#define SM_ROW_BYTES (KC * NTP * 8)         // 33024 B each
#define SM_AM1_OFF   SM_ROWS_OFF
#define SM_NF_OFF    (SM_ROWS_OFF + SM_ROW_BYTES)
#define SMEM_TOTAL   (SM_NF_OFF + SM_ROW_BYTES)   // ~106 KB

typedef unsigned long long u64;

// One o-pair step: R2 = fma2(am1d, g2, ones2); t2 = lg2(R2) per half
// (pair-allocated, no SASS movs); A2 += t2*wy2 + nfd*p2 ; B2 += t2*wz2 + nfd*q2
#define CPAIR(A2, B2, am1d, nfd, g2, wy2, wz2, p2, q2, ones2)           \
    asm("{\n\t"                                                          \
        ".reg .f32 r0, r1, t0, t1;\n\t"                                  \
        ".reg .b64 rr, tt;\n\t"                                          \
        "fma.rn.f32x2 rr, %2, %4, %9;\n\t"                               \
        "mov.b64 {r0, r1}, rr;\n\t"                                      \
        "lg2.approx.f32 t0, r0;\n\t"                                     \
        "lg2.approx.f32 t1, r1;\n\t"                                     \
        "mov.b64 tt, {t0, t1};\n\t"                                      \
        "fma.rn.f32x2 %0, tt, %5, %0;\n\t"                               \
        "fma.rn.f32x2 %1, tt, %6, %1;\n\t"                               \
        "fma.rn.f32x2 %0, %3, %7, %0;\n\t"                               \
        "fma.rn.f32x2 %1, %3, %8, %1;\n\t"                               \
        "}"                                                              \
        : "+l"(A2), "+l"(B2)                                             \
        : "l"(am1d), "l"(nfd), "l"(g2), "l"(wy2), "l"(wz2),              \
          "l"(p2), "l"(q2), "l"(ones2))

__global__ __launch_bounds__(THREADS, 1)
void NPU_main_kernel(const float* __restrict__ x, float* __restrict__ out) {
    extern __shared__ char smem[];
    float*  sG   = (float*)(smem + SM_G_OFF);
    float*  sWy  = (float*)(smem + SM_WY_OFF);
    float*  sWz  = (float*)(smem + SM_WZ_OFF);
    float*  sP   = (float*)(smem + SM_P_OFF);
    float*  sQ   = (float*)(smem + SM_Q_OFF);
    float2* sAm1 = (float2*)(smem + SM_AM1_OFF);   // [KC][NTP] (am1, am1)
    float2* sNf  = (float2*)(smem + SM_NF_OFF);    // [KC][NTP] (nf, nf)

    const int tid = threadIdx.x;
    const int n0  = blockIdx.x * NT;
    const int o0  = blockIdx.y * OT;
    const int to  = (tid & 15) * OR;   // col offset in tile
    const int tn  = (tid >> 4) * NR;   // row offset in tile

    const u64 ONES2 = 0x3F8000003F800000ULL;   // (1.0f, 1.0f)

    u64 A2[NR][2], B2[NR][2];
    #pragma unroll
    for (int r = 0; r < NR; r++)
        #pragma unroll
        for (int jp = 0; jp < 2; jp++) { A2[r][jp] = 0ULL; B2[r][jp] = 0ULL; }

    for (int c = 0; c < NCH; c++) {
        const int i0 = c * KC;
        __syncthreads();   // previous chunk fully consumed

        // ---- stage 5 weight planes (each: exactly one float4 per thread) ----
        {
            int ir = tid >> 4;            // 0..31
            int o4 = (tid & 15) * 4;
            int gsrc = (i0 + ir) * DIM + o0 + o4;
            int sdst = ir * OT + o4;
            *(float4*)&sG [sdst] = *(const float4*)&gGa[gsrc];
            *(float4*)&sWy[sdst] = *(const float4*)&gWy[gsrc];
            *(float4*)&sWz[sdst] = *(const float4*)&gWz[gsrc];
            *(float4*)&sP [sdst] = *(const float4*)&gP [gsrc];
            *(float4*)&sQ [sdst] = *(const float4*)&gQ [gsrc];
        }
        // ---- stage rows pre-duplicated: (am1,am1) and (nf,nf) ----
        #pragma unroll
        for (int k = tid; k < NT * KC / 4; k += THREADS) {
            int n  = k >> 3;              // 0..127
            int i4 = (k & 7) * 4;
            float4 xv = *(const float4*)&x[(n0 + n) * DIM + i0 + i4];
            float a0 = (fabsf(xv.x) + 1e-36f) - 1.0f;
            float a1 = (fabsf(xv.y) + 1e-36f) - 1.0f;
            float a2 = (fabsf(xv.z) + 1e-36f) - 1.0f;
            float a3 = (fabsf(xv.w) + 1e-36f) - 1.0f;
            float f0 = xv.x < 0.0f ? 1.0f : 0.0f;
            float f1 = xv.y < 0.0f ? 1.0f : 0.0f;
            float f2 = xv.z < 0.0f ? 1.0f : 0.0f;
            float f3 = xv.w < 0.0f ? 1.0f : 0.0f;
            sAm1[(i4 + 0) * NTP + n] = make_float2(a0, a0);
            sAm1[(i4 + 1) * NTP + n] = make_float2(a1, a1);
            sAm1[(i4 + 2) * NTP + n] = make_float2(a2, a2);
            sAm1[(i4 + 3) * NTP + n] = make_float2(a3, a3);
            sNf [(i4 + 0) * NTP + n] = make_float2(f0, f0);
            sNf [(i4 + 1) * NTP + n] = make_float2(f1, f1);
            sNf [(i4 + 2) * NTP + n] = make_float2(f2, f2);
            sNf [(i4 + 3) * NTP + n] = make_float2(f3, f3);
        }
        __syncthreads();

        // ---- hot loop ----
        #pragma unroll 2
        for (int i = 0; i < KC; i++) {
            // weights for 4 cols = 2 packed pairs each
            ulonglong2 g2  = *(const ulonglong2*)&sG [i * OT + to];
            ulonglong2 wy2 = *(const ulonglong2*)&sWy[i * OT + to];
            ulonglong2 wz2 = *(const ulonglong2*)&sWz[i * OT + to];
            ulonglong2 p2  = *(const ulonglong2*)&sP [i * OT + to];
            ulonglong2 q2  = *(const ulonglong2*)&sQ [i * OT + to];

            u64 am1d[NR], nfd[NR];
            #pragma unroll
            for (int r = 0; r < NR; r++) {
                am1d[r] = *(const u64*)&sAm1[i * NTP + tn + r];
                nfd[r]  = *(const u64*)&sNf [i * NTP + tn + r];
            }

            #pragma unroll
            for (int r = 0; r < NR; r++) {
                CPAIR(A2[r][0], B2[r][0], am1d[r], nfd[r],
                      g2.x, wy2.x, wz2.x, p2.x, q2.x, ONES2);
                CPAIR(A2[r][1], B2[r][1], am1d[r], nfd[r],
                      g2.y, wy2.y, wz2.y, p2.y, q2.y, ONES2);
            }
        }
    }

    // ---- epilogue: out = exp(A) * cos(B) ----
    #pragma unroll
    for (int r = 0; r < NR; r++) {
        float a[OR], b[OR];
        #pragma unroll
        for (int jp = 0; jp < 2; jp++) {
            a[2*jp+0] = __uint_as_float((unsigned int)(A2[r][jp] & 0xffffffffULL));
            a[2*jp+1] = __uint_as_float((unsigned int)(A2[r][jp] >> 32));
            b[2*jp+0] = __uint_as_float((unsigned int)(B2[r][jp] & 0xffffffffULL));
            b[2*jp+1] = __uint_as_float((unsigned int)(B2[r][jp] >> 32));
        }
        float4 v;
        v.x = expf(a[0]) * cosf(b[0]);
        v.y = expf(a[1]) * cosf(b[1]);
        v.z = expf(a[2]) * cosf(b[2]);
        v.w = expf(a[3]) * cosf(b[3]);
        *(float4*)&out[(n0 + tn + r) * DIM + o0 + to] = v;
    }
}

extern "C" void kernel_launch(void* const* d_in, const int* in_sizes, int n_in,
                              void* d_out, int out_size) {
    const float* x  = (const float*)d_in[0];
    const float* Wr = (const float*)d_in[1];
    const float* Wi = (const float*)d_in[2];
    const float* G  = (const float*)d_in[3];
    float* out = (float*)d_out;
    (void)in_sizes; (void)n_in; (void)out_size;

    NPU_prep_kernel<<<(DIM * DIM + 255) / 256, 256>>>(Wr, Wi, G);

    cudaFuncSetAttribute(NPU_main_kernel,
                         cudaFuncAttributeMaxDynamicSharedMemorySize, SMEM_TOTAL);
    dim3 grid(N_ROWS / NT, DIM / OT);
    NPU_main_kernel<<<grid, THREADS, SMEM_TOTAL>>>(x, out);
}

// round 6
// speedup vs baseline: 1.0041x; 1.0041x over previous
#include <cuda_runtime.h>
#include <math.h>

#define N_ROWS 8192
#define DIM    128

#define NT 56            // rows per block (147 n-tiles -> 294 blocks = 2/SM wave)
#define OT 64            // cols per block
#define KC 32            // i-chunk staged in smem
#define NCH (DIM / KC)   // 4 chunks
#define THREADS 224      // (OT/OR)=16 x (NT/NR)=14
#define NR 4             // rows per thread
#define OR 4             // cols per thread
#define NTP 57           // padded float2 row stride
#define NTILES ((N_ROWS + NT - 1) / NT)   // 147

// ---- packed weights (prep kernel output) ----
// gG   : g (clipped)
// gWyz : (ln2*Wr, ln2*Wi)   -> multiplies lg2(R) into (A,B) with one FFMA2
// gPQ  : (-pi*g*Wi, pi*g*Wr)-> sign (x<0) contribution to (A,B), one FFMA2
__device__ float  gG  [DIM * DIM];
__device__ float2 gWyz[DIM * DIM];
__device__ float2 gPQ [DIM * DIM];

__global__ void NPU_prep_kernel(const float* __restrict__ Wr,
                                const float* __restrict__ Wi,
                                const float* __restrict__ G) {
    int idx = blockIdx.x * blockDim.x + threadIdx.x;
    if (idx >= DIM * DIM) return;
    float g = fminf(fmaxf(G[idx], 0.0f), 1.0f);
    float wr = Wr[idx];
    float wi = Wi[idx];
    const float LN2 = 0.69314718055994530942f;
    const float PI  = 3.14159265358979323846f;
    gG[idx]   = g;
    gWyz[idx] = make_float2(LN2 * wr, LN2 * wi);
    gPQ[idx]  = make_float2(-PI * g * wi, PI * g * wr);
}

// ---- smem layout (~55KB -> 2 blocks/SM) ----
#define SM_G_BYTES   (KC * OT * 4)     //  8192
#define SM_WYZ_BYTES (KC * OT * 8)     // 16384
#define SM_PQ_BYTES  (KC * OT * 8)     // 16384
#define SM_ROW_BYTES (KC * NTP * 8)    // 14592
#define SM_WYZ_OFF   (SM_G_BYTES)
#define SM_PQ_OFF    (SM_WYZ_OFF + SM_WYZ_BYTES)
#define SM_ROW_OFF   (SM_PQ_OFF + SM_PQ_BYTES)
#define SMEM_TOTAL   (SM_ROW_OFF + SM_ROW_BYTES)

#define FMA_F32X2(d, a, b) \
    asm("fma.rn.f32x2 %0, %1, %2, %0;" : "+l"(d) : "l"(a), "l"(b))

#define PACK_DUP(d, s) \
    asm("mov.b64 %0, {%1, %1};" : "=l"(d) : "r"(s))

__global__ __launch_bounds__(THREADS, 2)
void NPU_main_kernel(const float* __restrict__ x, float* __restrict__ out) {
    extern __shared__ char smem[];
    float*  sG   = (float*) smem;                          // [KC][OT]
    float2* sWyz = (float2*)(smem + SM_WYZ_OFF);           // [KC][OT]
    float2* sPQ  = (float2*)(smem + SM_PQ_OFF);            // [KC][OT]
    float2* sRow = (float2*)(smem + SM_ROW_OFF);           // [KC][NTP] (am1, negf)

    const int tid = threadIdx.x;
    const int n0  = blockIdx.x * NT;
    const int o0  = blockIdx.y * OT;
    const int to  = (tid & 15) * OR;   // col offset in tile
    const int tn  = (tid >> 4) * NR;   // row offset in tile

    unsigned long long AB[NR][OR];
    #pragma unroll
    for (int r = 0; r < NR; r++)
        #pragma unroll
        for (int j = 0; j < OR; j++) AB[r][j] = 0ULL;

    for (int c = 0; c < NCH; c++) {
        const int i0 = c * KC;
        __syncthreads();   // previous chunk fully consumed

        // ---- stage weights ----
        for (int k = tid; k < KC * OT / 4; k += THREADS) {     // 512 float4s of g
            int ir = k >> 4;              // 0..31
            int o4 = (k & 15) * 4;
            *(float4*)&sG[ir * OT + o4] =
                *(const float4*)&gG[(i0 + ir) * DIM + o0 + o4];
        }
        for (int k = tid; k < KC * OT / 2; k += THREADS) {     // 1024 float4s each
            int ir = k >> 5;              // 0..31
            int o2 = (k & 31) * 2;
            *(float4*)&sWyz[ir * OT + o2] =
                *(const float4*)&gWyz[(i0 + ir) * DIM + o0 + o2];
            *(float4*)&sPQ[ir * OT + o2] =
                *(const float4*)&gPQ[(i0 + ir) * DIM + o0 + o2];
        }
        // ---- stage rows: am1 = |x|+eps-1, negf = (x<0) ; [i][n] layout ----
        for (int k = tid; k < NT * KC / 4; k += THREADS) {     // 448 = 2 iters exactly
            int n  = k >> 3;              // 0..55
            int i4 = (k & 7) * 4;
            int ng = n0 + n;
            if (ng >= N_ROWS) ng = N_ROWS - 1;   // clamp; stores guarded later
            float4 xv = *(const float4*)&x[ng * DIM + i0 + i4];
            sRow[(i4 + 0) * NTP + n] =
                make_float2((fabsf(xv.x) + 1e-36f) - 1.0f, xv.x < 0.0f ? 1.0f : 0.0f);
            sRow[(i4 + 1) * NTP + n] =
                make_float2((fabsf(xv.y) + 1e-36f) - 1.0f, xv.y < 0.0f ? 1.0f : 0.0f);
            sRow[(i4 + 2) * NTP + n] =
                make_float2((fabsf(xv.z) + 1e-36f) - 1.0f, xv.z < 0.0f ? 1.0f : 0.0f);
            sRow[(i4 + 3) * NTP + n] =
                make_float2((fabsf(xv.w) + 1e-36f) - 1.0f, xv.w < 0.0f ? 1.0f : 0.0f);
        }
        __syncthreads();

        // ---- hot loop (R3 codegen: scalar lg2, FFMA2 accumulate) ----
        #pragma unroll 2
        for (int i = 0; i < KC; i++) {
            float4 gv = *(const float4*)&sG[i * OT + to];
            ulonglong2 w01 = *(const ulonglong2*)&sWyz[i * OT + to];
            ulonglong2 w23 = *(const ulonglong2*)&sWyz[i * OT + to + 2];
            ulonglong2 p01 = *(const ulonglong2*)&sPQ [i * OT + to];
            ulonglong2 p23 = *(const ulonglong2*)&sPQ [i * OT + to + 2];
            unsigned long long wj[OR] = {w01.x, w01.y, w23.x, w23.y};
            unsigned long long pj[OR] = {p01.x, p01.y, p23.x, p23.y};
            float gj[OR] = {gv.x, gv.y, gv.z, gv.w};

            float2 rv[NR];
            unsigned long long nfnf[NR];
            #pragma unroll
            for (int r = 0; r < NR; r++) {
                rv[r] = sRow[i * NTP + tn + r];
                PACK_DUP(nfnf[r], __float_as_uint(rv[r].y));
            }

            #pragma unroll
            for (int r = 0; r < NR; r++) {
                #pragma unroll
                for (int j = 0; j < OR; j++) {
                    float R = fmaf(rv[r].x, gj[j], 1.0f);  // a*g + (1-g)
                    float t = __log2f(R);                   // MUFU.LG2
                    unsigned long long tt;
                    PACK_DUP(tt, __float_as_uint(t));
                    FMA_F32X2(AB[r][j], tt, wj[j]);         // (A,B) += t*(wy,wz)
                    FMA_F32X2(AB[r][j], nfnf[r], pj[j]);    // (A,B) += nf*(Pa,Q)
                }
            }
        }
    }

    // ---- epilogue: out = exp(A) * cos(B), guarded for partial last tile ----
    #pragma unroll
    for (int r = 0; r < NR; r++) {
        int ng = n0 + tn + r;
        if (ng >= N_ROWS) continue;
        float4 v;
        float av[OR], bv[OR];
        #pragma unroll
        for (int j = 0; j < OR; j++) {
            av[j] = __uint_as_float((unsigned int)(AB[r][j] & 0xffffffffULL));
            bv[j] = __uint_as_float((unsigned int)(AB[r][j] >> 32));
        }
        v.x = expf(av[0]) * cosf(bv[0]);
        v.y = expf(av[1]) * cosf(bv[1]);
        v.z = expf(av[2]) * cosf(bv[2]);
        v.w = expf(av[3]) * cosf(bv[3]);
        *(float4*)&out[ng * DIM + o0 + to] = v;
    }
}

extern "C" void kernel_launch(void* const* d_in, const int* in_sizes, int n_in,
                              void* d_out, int out_size) {
    const float* x  = (const float*)d_in[0];
    const float* Wr = (const float*)d_in[1];
    const float* Wi = (const float*)d_in[2];
    const float* G  = (const float*)d_in[3];
    float* out = (float*)d_out;
    (void)in_sizes; (void)n_in; (void)out_size;

    NPU_prep_kernel<<<(DIM * DIM + 255) / 256, 256>>>(Wr, Wi, G);

    cudaFuncSetAttribute(NPU_main_kernel,
                         cudaFuncAttributeMaxDynamicSharedMemorySize, SMEM_TOTAL);
    dim3 grid(NTILES, DIM / OT);
    NPU_main_kernel<<<grid, THREADS, SMEM_TOTAL>>>(x, out);
}